// round 16
// baseline (speedup 1.0000x reference)
#include <cuda_runtime.h>
#include <math.h>

#define BATCH   16
#define NPB     36864      // boxes per batch = 64*64*9
#define NTOT    (BATCH * NPB)
#define THREADS 1024
#define TOPN    300
#define NGT     64
#define TPOS    64
#define NBUCK   4096
#define CHK     512        // NMS chunk size

// L2-resident scratch (no cudaMalloc allowed)
__device__ float4             g_boxes[NTOT];
__device__ unsigned           g_k30[NTOT];
__device__ unsigned           g_hist[BATCH * NBUCK];
__device__ unsigned           g_cum[BATCH * (NBUCK + 1)];
__device__ unsigned           g_bpos[BATCH * NBUCK];
__device__ unsigned long long g_tmp[NTOT];
__device__ unsigned long long g_srt[NTOT];

// K5 dynamic smem (u32 units): kbox float4[512] + mask u32[512*16]
#define OFF_MASK  2048
#define DYN_U32   10240
#define DYN_BYTES (DYN_U32 * 4)

// bucket from descending key30 (monotone coarsening): uniform in score VALUE.
__device__ __forceinline__ unsigned bucket_of(unsigned key30) {
    float s = __uint_as_float(0x3F7FFFFFu - key30);
    unsigned q = (unsigned)__fmul_rn(s, 4096.f);
    if (q > 4095u) q = 4095u;
    return 4095u - q;
}

// Exact-threshold suppression test: guard band + exact division fallback.
__device__ __forceinline__ bool suppress_test(float4 sb, float sa, float4 bx, float ab) {
    float yy1 = fmaxf(sb.x, bx.x);
    float xx1 = fmaxf(sb.y, bx.y);
    float yy2 = fminf(sb.z, bx.z);
    float xx2 = fminf(sb.w, bx.w);
    float ih  = fmaxf(__fsub_rn(yy2, yy1), 0.f);
    float iw  = fmaxf(__fsub_rn(xx2, xx1), 0.f);
    float inter = __fmul_rn(ih, iw);
    float denom = __fadd_rn(__fsub_rn(__fadd_rn(sa, ab), inter), 1e-7f);
    float e = __fmaf_rn(-0.5f, denom, inter);
    float margin = __fmul_rn(denom, 1e-4f);
    if (e < -margin) return false;
    if (e >  margin) return true;
    return __fdiv_rn(inter, denom) >= 0.5f;       // exact reference semantics
}

// ===================== K0: zero histogram ==============================
__global__ void k0_zero() {
    int i = blockIdx.x * blockDim.x + threadIdx.x;
    if (i < BATCH * NBUCK) g_hist[i] = 0;
}

// ===================== K1: decode + key + global hist ==================
__global__ void __launch_bounds__(THREADS)
k1_decode(const float* __restrict__ deltas,
          const float* __restrict__ labels,
          const float* __restrict__ anchors)
{
    int gi = blockIdx.x * THREADS + threadIdx.x;   // 0 .. NTOT-1
    int b = gi / NPB;
    float4 a = ((const float4*)anchors)[gi];
    float4 d = ((const float4*)deltas)[gi];
    float ah  = __fsub_rn(a.z, a.x);
    float aw  = __fsub_rn(a.w, a.y);
    float acy = __fadd_rn(a.x, __fmul_rn(0.5f, ah));
    float acx = __fadd_rn(a.y, __fmul_rn(0.5f, aw));
    float h   = __fmul_rn(expf(d.z), ah);
    float w   = __fmul_rn(expf(d.w), aw);
    float cy  = __fadd_rn(__fmul_rn(d.x, ah), acy);
    float cx  = __fadd_rn(__fmul_rn(d.y, aw), acx);
    float y1  = __fsub_rn(cy, __fmul_rn(0.5f, h));
    float x1  = __fsub_rn(cx, __fmul_rn(0.5f, w));
    g_boxes[gi] = make_float4(y1, x1, __fadd_rn(y1, h), __fadd_rn(x1, w));
    unsigned key30 = 0x3F7FFFFFu - __float_as_uint(labels[gi]);
    g_k30[gi] = key30;
    atomicAdd(&g_hist[b * NBUCK + bucket_of(key30)], 1u);
}

// ===================== K2: per-batch exclusive scan ====================
__global__ void __launch_bounds__(THREADS)
k2_scan()
{
    __shared__ unsigned s_warp[32];
    const int b = blockIdx.x;
    const int t = threadIdx.x;
    const int lane = t & 31, wid = t >> 5;
    const unsigned* hist = g_hist + b * NBUCK;
    unsigned* cum  = g_cum  + b * (NBUCK + 1);
    unsigned* bpos = g_bpos + b * NBUCK;

    unsigned v[4], sum = 0;
    #pragma unroll
    for (int j = 0; j < 4; ++j) v[j] = hist[t * 4 + j];
    unsigned e[4];
    #pragma unroll
    for (int j = 0; j < 4; ++j) { e[j] = sum; sum += v[j]; }
    unsigned x = sum;
    #pragma unroll
    for (int o = 1; o < 32; o <<= 1) {
        unsigned y = __shfl_up_sync(0xffffffffu, x, o);
        if (lane >= o) x += y;
    }
    if (lane == 31) s_warp[wid] = x;
    __syncthreads();
    if (t < 32) {
        unsigned wsum = s_warp[t], xx = wsum;
        #pragma unroll
        for (int o = 1; o < 32; o <<= 1) {
            unsigned y = __shfl_up_sync(0xffffffffu, xx, o);
            if (t >= o) xx += y;
        }
        s_warp[t] = xx - wsum;
    }
    __syncthreads();
    unsigned prefix = s_warp[wid] + (x - sum);
    #pragma unroll
    for (int j = 0; j < 4; ++j) {
        cum[t * 4 + j]  = prefix + e[j];
        bpos[t * 4 + j] = prefix + e[j];
    }
    if (t == THREADS - 1) cum[NBUCK] = prefix + sum;
}

// ===================== K3: counting-sort scatter =======================
__global__ void __launch_bounds__(THREADS)
k3_scatter()
{
    int gi = blockIdx.x * THREADS + threadIdx.x;
    int b = gi / NPB;
    int i = gi - b * NPB;
    unsigned key30 = g_k30[gi];
    unsigned bk = bucket_of(key30);
    unsigned slot = atomicAdd(&g_bpos[b * NBUCK + bk], 1u);
    g_tmp[(size_t)b * NPB + slot] = ((unsigned long long)key30 << 16) | (unsigned)i;
}

// ===================== K4: per-bucket rank sort ========================
__global__ void __launch_bounds__(THREADS)
k4_sort()
{
    int gid = blockIdx.x * THREADS + threadIdx.x;   // 0 .. 65535
    int b  = gid >> 12;
    int bk = gid & (NBUCK - 1);
    const unsigned* cum = g_cum + b * (NBUCK + 1);
    int lo = (int)cum[bk], hi = (int)cum[bk + 1];
    const unsigned long long* src = g_tmp + (size_t)b * NPB;
    unsigned long long*       dst = g_srt + (size_t)b * NPB;
    for (int i2 = lo; i2 < hi; ++i2) {
        unsigned long long v = src[i2];
        int r = 0;
        for (int j2 = lo; j2 < hi; ++j2) r += (src[j2] < v);
        dst[lo + r] = v;
    }
}

// ===================== K5: chunked greedy NMS + epilogue ===============
__global__ void __launch_bounds__(THREADS, 1)
k5_nms(const float* __restrict__ gt, float* __restrict__ out)
{
    extern __shared__ unsigned s_dyn[];
    float4*   s_kbox = (float4*)s_dyn;               // 512 compacted boxes
    unsigned* s_mask = s_dyn + OFF_MASK;             // 512 rows x 16 words

    __shared__ float4 s_sel[TOPN];
    __shared__ float  s_sela[TOPN];
    __shared__ float4 s_nms[TOPN];
    __shared__ float  s_merged[TOPN];
    __shared__ int    s_gtbest[TOPN];
    __shared__ float4 s_gt4[NGT];
    __shared__ unsigned s_warp[32];
    __shared__ unsigned s_kalA[16], s_kalB[16];
    __shared__ int    s_ncur, s_M;

    const int b = blockIdx.x;
    const int t = threadIdx.x;
    const int lane = t & 31, wid = t >> 5;
    const int p    = t & (CHK - 1);
    const int grp  = t >> 9;

    const float4* boxes = g_boxes + (size_t)b * NPB;
    const unsigned long long* srt = g_srt + (size_t)b * NPB;

    if (t == 0) s_ncur = 0;
    __syncthreads();

    for (int pos = 0; pos < NPB; pos += CHK) {
        if (s_ncur >= TOPN) break;            // uniform (post-sync)
        int nc = s_ncur;

        // ---- load candidate (both groups hold the same box) ----
        unsigned gidx = (unsigned)(srt[pos + p] & 0xFFFFu);
        float4 bx = boxes[gidx];
        float  ab = __fmul_rn(__fsub_rn(bx.z, bx.x), __fsub_rn(bx.w, bx.y));

        // ---- split prekill: grpA tests [0,ncA), grpB tests [ncA,nc) ----
        int ncA = (nc + 1) >> 1;
        int j0 = grp ? ncA : 0;
        int j1 = grp ? nc  : ncA;
        bool kill = false;
        for (int j = j0; j < j1 && !kill; ++j)
            kill = suppress_test(s_sel[j], s_sela[j], bx, ab);
        unsigned kb = __ballot_sync(0xffffffffu, kill);
        if (lane == 0) { if (grp == 0) s_kalA[wid] = kb; else s_kalB[wid - 16] = kb; }
        __syncthreads();

        // ---- merge kill info, compact alive (order-preserving) ----
        bool alive = false;
        if (grp == 0) {
            unsigned kw = s_kalA[p >> 5] | s_kalB[p >> 5];
            alive = !((kw >> (p & 31)) & 1u);
        }
        unsigned bal = __ballot_sync(0xffffffffu, alive);
        if (lane == 0) s_warp[wid] = __popc(bal);
        __syncthreads();
        if (t < 32) {
            unsigned wsum = s_warp[t], xx = wsum;
            #pragma unroll
            for (int o = 1; o < 32; o <<= 1) {
                unsigned y = __shfl_up_sync(0xffffffffu, xx, o);
                if (t >= o) xx += y;
            }
            s_warp[t] = xx - wsum;
            if (t == 31) s_M = (int)xx;
        }
        __syncthreads();
        int M = s_M;
        if (alive) {
            int cpos = (int)s_warp[wid] + __popc(bal & ((1u << lane) - 1u));
            s_kbox[cpos] = bx;
        }
        for (int i = t; i < M * 16; i += THREADS) s_mask[i] = 0;
        __syncthreads();
        if (M == 0) continue;                 // uniform

        // ---- pair enumeration among compacted survivors ----
        if (M >= 2 && p < M) {
            int half = M >> 1;
            float4 P = s_kbox[p];
            float pa = __fmul_rn(__fsub_rn(P.z, P.x), __fsub_rn(P.w, P.y));
            for (int d = 1 + grp; d <= half; d += 2) {
                int o = p + d; if (o >= M) o -= M;
                int a = p < o ? p : o;        // earlier = suppressor
                int c = p < o ? o : p;
                float4 C = s_kbox[o];
                float ca = __fmul_rn(__fsub_rn(C.z, C.x), __fsub_rn(C.w, C.y));
                if (suppress_test(P, pa, C, ca))
                    atomicOr(&s_mask[a * 16 + (c >> 5)], 1u << (c & 31));
            }
        }
        __syncthreads();

        // ---- warp0 greedy resolution over the bitmask (no block BARs) ----
        if (t < 32) {
            unsigned dead = 0;
            unsigned aliveW = 0;
            if (t < 16) {
                int bb = t * 32;
                int rem = M - bb;
                aliveW = (rem >= 32) ? 0xffffffffu
                       : (rem > 0 ? ((1u << rem) - 1u) : 0u);
            }
            int n = nc;
            for (int w = 0; w < 16 && n < TOPN; ++w) {
                unsigned cur = __shfl_sync(0xffffffffu, aliveW & ~dead, w);
                while (cur && n < TOPN) {
                    int bitp = __ffs(cur) - 1;
                    int i = w * 32 + bitp;
                    cur &= cur - 1;
                    if (t == 0) {
                        float4 sb = s_kbox[i];
                        s_sel[n] = sb;
                        s_sela[n] = __fmul_rn(__fsub_rn(sb.z, sb.x),
                                              __fsub_rn(sb.w, sb.y));
                    }
                    n++;
                    unsigned row = (t < 16) ? s_mask[i * 16 + t] : 0u;
                    dead |= row;
                    unsigned rw = __shfl_sync(0xffffffffu, row, w);
                    cur &= ~rw;
                }
            }
            if (t == 0) s_ncur = n;
        }
        __syncthreads();
    }
    __syncthreads();
    const int nsel = s_ncur;

    // ---- Phase D: clip, select_rois, rank, emit ----
    for (int j = t; j < TOPN; j += THREADS) {
        float4 bxo = make_float4(0.f, 0.f, 0.f, 0.f);
        if (j < nsel) {
            float4 vv = s_sel[j];
            bxo.x = fminf(fmaxf(vv.x, 0.f), 1.f);
            bxo.y = fminf(fmaxf(vv.y, 0.f), 1.f);
            bxo.z = fminf(fmaxf(vv.z, 0.f), 1.f);
            bxo.w = fminf(fmaxf(vv.w, 0.f), 1.f);
        }
        s_nms[j] = bxo;
    }
    for (int j = t; j < NGT; j += THREADS) {
        s_gt4[j] = ((const float4*)gt)[(size_t)b * NGT + j];
    }
    __syncthreads();

    if (t < TOPN) {
        float4 a = s_nms[t];
        float aa = __fmul_rn(__fsub_rn(a.z, a.x), __fsub_rn(a.w, a.y));
        float mg = -1.f; int bi = 0;
        #pragma unroll 4
        for (int g = 0; g < NGT; ++g) {
            float4 gb = s_gt4[g];
            float yy1 = fmaxf(a.x, gb.x);
            float xx1 = fmaxf(a.y, gb.y);
            float yy2 = fminf(a.z, gb.z);
            float xx2 = fminf(a.w, gb.w);
            float inter = __fmul_rn(fmaxf(__fsub_rn(yy2, yy1), 0.f),
                                    fmaxf(__fsub_rn(xx2, xx1), 0.f));
            float gba = __fmul_rn(__fsub_rn(gb.z, gb.x), __fsub_rn(gb.w, gb.y));
            float denom = __fadd_rn(__fsub_rn(__fadd_rn(aa, gba), inter), 1e-7f);
            float iou = __fdiv_rn(inter, denom);
            if (iou > mg) { mg = iou; bi = g; }
        }
        s_merged[t] = mg; s_gtbest[t] = bi;
    }
    __syncthreads();

    if (t < TOPN) {
        float mg = s_merged[t];
        int r = 0;
        for (int j = 0; j < TOPN; ++j) {
            float mj = s_merged[j];
            if (mj > mg || (mj == mg && j < t)) ++r;
        }
        if (r < TPOS) {
            float4 a = s_nms[t];
            float* roi = out + ((size_t)b * 128 + r) * 4;
            roi[0] = a.x; roi[1] = a.y; roi[2] = a.z; roi[3] = a.w;
            out[(size_t)BATCH * 128 * 4 + (size_t)b * TPOS + r] = (float)s_gtbest[t];
        }
    }
    for (int j = t; j < 64 * 4; j += THREADS) {
        out[((size_t)b * 128 + TPOS) * 4 + j] = 0.f;
    }
}

extern "C" void kernel_launch(void* const* d_in, const int* in_sizes, int n_in,
                              void* d_out, int out_size) {
    const float* deltas  = (const float*)d_in[0];
    const float* labels  = (const float*)d_in[1];
    const float* anchors = (const float*)d_in[2];
    const float* gt      = (const float*)d_in[3];
    float* out = (float*)d_out;
    cudaFuncSetAttribute(k5_nms, cudaFuncAttributeMaxDynamicSharedMemorySize,
                         DYN_BYTES);
    k0_zero<<<(BATCH * NBUCK + 1023) / 1024, 1024>>>();
    k1_decode<<<NTOT / THREADS, THREADS>>>(deltas, labels, anchors);
    k2_scan<<<BATCH, THREADS>>>();
    k3_scatter<<<NTOT / THREADS, THREADS>>>();
    k4_sort<<<(BATCH * NBUCK) / THREADS, THREADS>>>();
    k5_nms<<<BATCH, THREADS, DYN_BYTES>>>(gt, out);
}